// round 1
// baseline (speedup 1.0000x reference)
#include <cuda_runtime.h>

// Problem constants (from reference)
#define RR 200      // rules
#define NN 16       // padded graph size
#define FF 512      // feature dim
#define DD 128      // out dim
#define NUM_LAYERS 3
#define BB 32
#define LL 128
#define TOKENS (BB*LL)

// Per-rule pooled outputs: [200][128] fp32 scratch (device global, no alloc)
__device__ float g_out_r[RR * DD];

// Dynamic smem layout (floats):
//   e_s   [16*512]  = 8192
//   msg_s [16*512]  = 8192
//   a_s   [16*16]   = 256
//   m_s   [16]      = 16
//   part  [2*128]   = 256
#define SMEM_FLOATS (NN*FF + NN*FF + NN*NN + NN + 2*DD)
#define SMEM_BYTES  (SMEM_FLOATS * 4)

__global__ void __launch_bounds__(256, 1) rule_gnn_kernel(
    const float* __restrict__ adj,         // [200,16,16]
    const float* __restrict__ init_embed,  // [200,16,512]
    const float* __restrict__ node_mask,   // [200,16]
    const float* __restrict__ W_ll,        // [3,512,512]
    const float* __restrict__ b_ll,        // [3,512]
    const float* __restrict__ W_lo,        // [3,512,128]
    const float* __restrict__ b_lo)        // [3,128]
{
    extern __shared__ float sm[];
    float* e_s   = sm;                   // [16][512]
    float* msg_s = e_s + NN*FF;          // [16][512]
    float* a_s   = msg_s + NN*FF;        // [16][16]
    float* m_s   = a_s + NN*NN;          // [16]
    float* part  = m_s + NN;             // [2][128]

    const int rule = blockIdx.x;
    const int t = threadIdx.x;

    // ---- load rule-local data into smem ----
    if (t < NN*NN) a_s[t] = adj[rule*NN*NN + t];
    if (t < NN)    m_s[t] = node_mask[rule*NN + t];
    {
        // 16*512 floats = 2048 float4, 256 threads -> 8 each, coalesced
        const float4* src = (const float4*)(init_embed + (size_t)rule*NN*FF);
        float4* dst = (float4*)e_s;
        #pragma unroll
        for (int i = 0; i < 8; i++) dst[t + 256*i] = src[t + 256*i];
    }
    __syncthreads();

    float out_acc = 0.f;
    const int d    = t & 127;   // output-dim lane for pooled path
    const int half = t >> 7;    // which 8-row group of nodes

    for (int l = 0; l < NUM_LAYERS; l++) {
        // ================= msg = a @ e  (16x16 @ 16x512) =================
        {
            const int i  = t >> 4;     // node row 0..15
            const int c4 = t & 15;     // column-quad id
            float arow[16];
            #pragma unroll
            for (int j = 0; j < 16; j++) arow[j] = a_s[i*16 + j];
            #pragma unroll
            for (int blk = 0; blk < 8; blk++) {
                const int c = c4*4 + blk*64;
                float4 acc = make_float4(0.f, 0.f, 0.f, 0.f);
                #pragma unroll
                for (int j = 0; j < 16; j++) {
                    float4 ev = *(const float4*)(e_s + j*FF + c);
                    acc.x += arow[j]*ev.x; acc.y += arow[j]*ev.y;
                    acc.z += arow[j]*ev.z; acc.w += arow[j]*ev.w;
                }
                *(float4*)(msg_s + i*FF + c) = acc;
            }
        }
        __syncthreads();   // msg ready; old e free to overwrite

        // ====== pooled contrib: sum_i tanh(msg @ W_lo + b_lo)_i * m_i ======
        {
            const float* W = W_lo + l*FF*DD;
            const int i0 = half*8;
            float acc[8];
            #pragma unroll
            for (int j = 0; j < 8; j++) acc[j] = 0.f;
            #pragma unroll 2
            for (int k = 0; k < FF; k += 4) {
                const float w0 = W[(k+0)*DD + d];
                const float w1 = W[(k+1)*DD + d];
                const float w2 = W[(k+2)*DD + d];
                const float w3 = W[(k+3)*DD + d];
                #pragma unroll
                for (int j = 0; j < 8; j++) {
                    float4 mv = *(const float4*)(msg_s + (i0+j)*FF + k);
                    acc[j] += mv.x*w0 + mv.y*w1 + mv.z*w2 + mv.w*w3;
                }
            }
            const float bb = b_lo[l*DD + d];
            float p = 0.f;
            #pragma unroll
            for (int j = 0; j < 8; j++)
                p += tanhf(acc[j] + bb) * m_s[i0 + j];
            part[half*DD + d] = p;
        }

        // ============ e = relu(msg @ W_ll + b_ll)  (16x512 @ 512x512) ============
        {
            const float* W = W_ll + l*FF*FF;
            const int c0 = t, c1 = t + 256;
            float acc0[16], acc1[16];
            #pragma unroll
            for (int i = 0; i < 16; i++) { acc0[i] = 0.f; acc1[i] = 0.f; }
            #pragma unroll 1
            for (int k = 0; k < FF; k += 4) {
                const float wa0 = W[(k+0)*FF + c0], wb0 = W[(k+0)*FF + c1];
                const float wa1 = W[(k+1)*FF + c0], wb1 = W[(k+1)*FF + c1];
                const float wa2 = W[(k+2)*FF + c0], wb2 = W[(k+2)*FF + c1];
                const float wa3 = W[(k+3)*FF + c0], wb3 = W[(k+3)*FF + c1];
                #pragma unroll
                for (int i = 0; i < 16; i++) {
                    float4 mv = *(const float4*)(msg_s + i*FF + k);
                    acc0[i] += mv.x*wa0 + mv.y*wa1 + mv.z*wa2 + mv.w*wa3;
                    acc1[i] += mv.x*wb0 + mv.y*wb1 + mv.z*wb2 + mv.w*wb3;
                }
            }
            const float ba = b_ll[l*FF + c0], bb = b_ll[l*FF + c1];
            #pragma unroll
            for (int i = 0; i < 16; i++) {
                e_s[i*FF + c0] = fmaxf(acc0[i] + ba, 0.f);
                e_s[i*FF + c1] = fmaxf(acc1[i] + bb, 0.f);
            }
        }
        __syncthreads();   // e + part ready

        if (half == 0) out_acc += part[d] + part[DD + d];
        // part re-written only after NEXT layer's post-msg __syncthreads -> safe
    }

    if (t < DD) g_out_r[rule*DD + t] = out_acc;
}

// out[tok, d] = valid ? out_r[idx[tok], d] : 0  — float4 per thread
__global__ void gather_kernel(const int* __restrict__ idx, float4* __restrict__ out)
{
    const int gid = blockIdx.x * blockDim.x + threadIdx.x;  // over TOKENS*DD/4
    if (gid >= TOKENS * (DD/4)) return;
    const int tok = gid >> 5;          // 32 float4 per token
    const int d4  = gid & 31;
    const int r = idx[tok];
    float4 v = make_float4(0.f, 0.f, 0.f, 0.f);
    if (r < RR) v = ((const float4*)g_out_r)[r*(DD/4) + d4];
    out[gid] = v;
}

extern "C" void kernel_launch(void* const* d_in, const int* in_sizes, int n_in,
                              void* d_out, int out_size)
{
    const int*   idx        = (const int*)  d_in[0];  // [32,128] int32
    const float* adj        = (const float*)d_in[1];  // [200,16,16]
    const float* init_embed = (const float*)d_in[2];  // [200,16,512]
    const float* node_mask  = (const float*)d_in[3];  // [200,16]
    const float* W_ll       = (const float*)d_in[4];  // [3,512,512]
    const float* b_ll       = (const float*)d_in[5];  // [3,512]
    const float* W_lo       = (const float*)d_in[6];  // [3,512,128]
    const float* b_lo       = (const float*)d_in[7];  // [3,128]
    float* out = (float*)d_out;                       // [32,128,128]

    cudaFuncSetAttribute(rule_gnn_kernel,
                         cudaFuncAttributeMaxDynamicSharedMemorySize, SMEM_BYTES);

    rule_gnn_kernel<<<RR, 256, SMEM_BYTES>>>(adj, init_embed, node_mask,
                                             W_ll, b_ll, W_lo, b_lo);

    const int total4 = TOKENS * (DD/4);  // 131072
    gather_kernel<<<(total4 + 255)/256, 256>>>(idx, (float4*)out);
}

// round 4
// speedup vs baseline: 2.7942x; 2.7942x over previous
#include <cuda_runtime.h>
#include <cuda_bf16.h>
#include <cstdint>

// ---------------- problem constants ----------------
#define RR 200          // rules
#define NN 16           // nodes per graph
#define FF 512          // feature dim
#define DD 128          // out dim
#define NUML 3
#define TOKENS 4096     // 32*128
#define MTOT (RR*NN)    // 3200 rows
#define KSP (3*FF)      // 1536 split-K
#define KC 64           // K per smem chunk (64 bf16 = 128B rows)
#define NCHUNK (KSP/KC) // 24

// ---------------- device scratch ----------------
__device__ float g_out_r[RR*DD];
__device__ float g_e[MTOT*FF];
__device__ __nv_bfloat16 g_msg[MTOT*KSP];          // A' = [Ah|Ah|Al]
__device__ __nv_bfloat16 g_Wll[NUML*FF*KSP];       // B' = [Bh|Bl|Bh], [l][n][k']
__device__ __nv_bfloat16 g_Wlo[NUML*DD*KSP];

#define SWZ(x) ((x) ^ (((x) >> 3) & 0x70))

__device__ __forceinline__ uint32_t smem_u32(const void* p) {
    uint32_t a;
    asm("{ .reg .u64 t; cvta.to.shared.u64 t, %1; cvt.u32.u64 %0, t; }" : "=r"(a) : "l"(p));
    return a;
}
__device__ __forceinline__ void cp16(uint32_t dst, const void* src) {
    asm volatile("cp.async.cg.shared.global [%0], [%1], 16;" :: "r"(dst), "l"(src));
}
#define CP_COMMIT() asm volatile("cp.async.commit_group;" ::: "memory")
#define CP_WAIT(n)  asm volatile("cp.async.wait_group %0;" :: "n"(n) : "memory")

#define LDSM4(r, addr) \
    asm volatile("ldmatrix.sync.aligned.m8n8.x4.shared.b16 {%0,%1,%2,%3}, [%4];" \
        : "=r"((r)[0]), "=r"((r)[1]), "=r"((r)[2]), "=r"((r)[3]) : "r"(addr))

#define MMA16816(d, a, b0v, b1v) \
    asm volatile("mma.sync.aligned.m16n8k16.row.col.f32.bf16.bf16.f32 " \
        "{%0,%1,%2,%3}, {%4,%5,%6,%7}, {%8,%9}, {%0,%1,%2,%3};" \
        : "+f"((d)[0]), "+f"((d)[1]), "+f"((d)[2]), "+f"((d)[3]) \
        : "r"((a)[0]), "r"((a)[1]), "r"((a)[2]), "r"((a)[3]), "r"(b0v), "r"(b1v))

// ---------------- prep: split+transpose weights, zero out_r ----------------
__global__ void prep_kernel(const float* __restrict__ W_ll, const float* __restrict__ W_lo)
{
    int gid = blockIdx.x * 256 + threadIdx.x;
    if (gid < RR*DD) g_out_r[gid] = 0.f;
    if (gid < NUML*FF*FF) {
        int l = gid / (FF*FF), rem = gid % (FF*FF);
        int n = rem / FF, k = rem % FF;
        float w = W_ll[(size_t)(l*FF + k)*FF + n];
        __nv_bfloat16 hi = __float2bfloat16(w);
        __nv_bfloat16 lo = __float2bfloat16(w - __bfloat162float(hi));
        size_t base = (size_t)(l*FF + n) * KSP;
        g_Wll[base + k] = hi; g_Wll[base + FF + k] = lo; g_Wll[base + 2*FF + k] = hi;
    }
    if (gid < NUML*DD*FF) {
        int l = gid / (DD*FF), rem = gid % (DD*FF);
        int n = rem / FF, k = rem % FF;
        float w = W_lo[(size_t)(l*FF + k)*DD + n];
        __nv_bfloat16 hi = __float2bfloat16(w);
        __nv_bfloat16 lo = __float2bfloat16(w - __bfloat162float(hi));
        size_t base = (size_t)(l*DD + n) * KSP;
        g_Wlo[base + k] = hi; g_Wlo[base + FF + k] = lo; g_Wlo[base + 2*FF + k] = hi;
    }
}

// ---------------- msg = a@e (fp32), write split A' = [Ah|Ah|Al] ----------------
__global__ __launch_bounds__(256) void msg_kernel(const float* __restrict__ init_embed,
                                                  const float* __restrict__ adj, int layer)
{
    __shared__ float e_s[NN*FF];
    __shared__ float a_s[NN*NN];
    const int rule = blockIdx.x, t = threadIdx.x;
    const float* e_src = (layer == 0) ? (init_embed + (size_t)rule*NN*FF)
                                      : (g_e + (size_t)rule*NN*FF);
    a_s[t] = adj[rule*NN*NN + t];
    {
        const float4* s4 = (const float4*)e_src; float4* d4 = (float4*)e_s;
        #pragma unroll
        for (int i = 0; i < 8; i++) d4[t + 256*i] = s4[t + 256*i];
    }
    __syncthreads();
    const int i = t >> 4, q = t & 15;
    float ar[16];
    #pragma unroll
    for (int j = 0; j < 16; j++) ar[j] = a_s[i*16 + j];
    __nv_bfloat16* rowp = g_msg + (size_t)(rule*NN + i) * KSP;
    #pragma unroll
    for (int b = 0; b < 8; b++) {
        const int c = q*4 + b*64;
        float4 acc = make_float4(0.f, 0.f, 0.f, 0.f);
        #pragma unroll
        for (int j = 0; j < 16; j++) {
            float4 ev = *(const float4*)(e_s + j*FF + c);
            acc.x += ar[j]*ev.x; acc.y += ar[j]*ev.y;
            acc.z += ar[j]*ev.z; acc.w += ar[j]*ev.w;
        }
        __nv_bfloat16 h0 = __float2bfloat16(acc.x), h1 = __float2bfloat16(acc.y);
        __nv_bfloat16 h2 = __float2bfloat16(acc.z), h3 = __float2bfloat16(acc.w);
        __nv_bfloat16 l0 = __float2bfloat16(acc.x - __bfloat162float(h0));
        __nv_bfloat16 l1 = __float2bfloat16(acc.y - __bfloat162float(h1));
        __nv_bfloat16 l2 = __float2bfloat16(acc.z - __bfloat162float(h2));
        __nv_bfloat16 l3 = __float2bfloat16(acc.w - __bfloat162float(h3));
        __nv_bfloat162 hp0(h0, h1), hp1(h2, h3), lp0(l0, l1), lp1(l2, l3);
        uint2 hv = make_uint2(*(uint32_t*)&hp0, *(uint32_t*)&hp1);
        uint2 lv = make_uint2(*(uint32_t*)&lp0, *(uint32_t*)&lp1);
        *(uint2*)(rowp + c)        = hv;
        *(uint2*)(rowp + FF + c)   = hv;
        *(uint2*)(rowp + 2*FF + c) = lv;
    }
}

// ---------------- fused HMMA GEMM: D[128x128] = A'(128xK') @ B'^T ----------------
// blockIdx.y < 4 : ll tile y  (e = relu(D + b_ll))          [skipped when lo_only]
// blockIdx.y ==4 or lo_only : lo (out_r += pool16(tanh(D + b_lo) * mask))
#define SM_A0 0
#define SM_B0 16384
#define SM_A1 32768
#define SM_B1 49152
#define SM_BYTES 65536

__global__ __launch_bounds__(256, 1) void fused_gemm_kernel(
    int l, int lo_only,
    const float* __restrict__ b_ll, const float* __restrict__ b_lo,
    const float* __restrict__ mask)
{
    extern __shared__ char smem[];
    const uint32_t sb = smem_u32(smem);
    const int t = threadIdx.x, lid = t & 31, wid = t >> 5;
    const int warp_m = wid & 3, warp_n = wid >> 2;   // 4 x 2 warps -> 128 x 128
    const int mt = blockIdx.x;
    const int mode = (lo_only || blockIdx.y == 4) ? 1 : 0;
    const int nt = mode ? 0 : blockIdx.y;

    const __nv_bfloat16* Arow = g_msg + (size_t)mt * 128 * KSP;
    const __nv_bfloat16* Brow = (mode ? (g_Wlo + (size_t)l*DD*KSP)
                                      : (g_Wll + (size_t)l*FF*KSP + (size_t)nt*128*KSP));

    const uint32_t aoff[2] = {SM_A0, SM_A1}, boff[2] = {SM_B0, SM_B1};
    // per-thread load mapping: 4 int4 for A + 4 for B per chunk
    const int r_ld[4] = { (t + 0) >> 3, (t + 256) >> 3, (t + 512) >> 3, (t + 768) >> 3 };
    const int g_ld = t & 7;
    const uint32_t so_ld[4] = {
        SWZ((uint32_t)(r_ld[0]*128 + g_ld*16)), SWZ((uint32_t)(r_ld[1]*128 + g_ld*16)),
        SWZ((uint32_t)(r_ld[2]*128 + g_ld*16)), SWZ((uint32_t)(r_ld[3]*128 + g_ld*16)) };

    float acc[2][8][4];
    #pragma unroll
    for (int i = 0; i < 2; i++)
        #pragma unroll
        for (int j = 0; j < 8; j++)
            #pragma unroll
            for (int k = 0; k < 4; k++) acc[i][j][k] = 0.f;

    // prefetch chunk 0 -> buf 0
    #pragma unroll
    for (int u = 0; u < 4; u++) {
        const size_t gi = (size_t)r_ld[u] * KSP + g_ld*8;
        cp16(sb + SM_A0 + so_ld[u], Arow + gi);
        cp16(sb + SM_B0 + so_ld[u], Brow + gi);
    }
    CP_COMMIT();

    const int lid15 = lid & 15, lidh = lid >> 4;

    for (int c = 0; c < NCHUNK; c++) {
        const int s = c & 1;
        if (c + 1 < NCHUNK) {
            #pragma unroll
            for (int u = 0; u < 4; u++) {
                const size_t gi = (size_t)r_ld[u] * KSP + (c+1)*KC + g_ld*8;
                cp16(sb + aoff[s^1] + so_ld[u], Arow + gi);
                cp16(sb + boff[s^1] + so_ld[u], Brow + gi);
            }
            CP_COMMIT();
            CP_WAIT(1);
        } else {
            CP_WAIT(0);
        }
        __syncthreads();

        #pragma unroll
        for (int ks = 0; ks < 4; ks++) {
            const uint32_t grp = ks*2 + lidh;
            uint32_t af[2][4];
            #pragma unroll
            for (int m2 = 0; m2 < 2; m2++) {
                const uint32_t row = warp_m*32 + m2*16 + lid15;
                LDSM4(af[m2], sb + aoff[s] + SWZ(row*128 + grp*16));
            }
            #pragma unroll
            for (int n4 = 0; n4 < 4; n4++) {
                uint32_t bf[4];
                const uint32_t row = warp_n*64 + n4*16 + lid15;
                LDSM4(bf, sb + boff[s] + SWZ(row*128 + grp*16));
                #pragma unroll
                for (int m2 = 0; m2 < 2; m2++) {
                    MMA16816(acc[m2][n4*2],   af[m2], bf[0], bf[2]);
                    MMA16816(acc[m2][n4*2+1], af[m2], bf[1], bf[3]);
                }
            }
        }
        __syncthreads();
    }

    // ---------------- epilogue ----------------
    if (mode == 0) {
        const float* bias = b_ll + l*FF;
        #pragma unroll
        for (int m2 = 0; m2 < 2; m2++) {
            const int r0 = mt*128 + warp_m*32 + m2*16 + (lid >> 2);
            #pragma unroll
            for (int j = 0; j < 8; j++) {
                const int n = nt*128 + warp_n*64 + j*8 + (lid & 3)*2;
                const float bx = bias[n], by = bias[n+1];
                float2 v0, v1;
                v0.x = fmaxf(acc[m2][j][0] + bx, 0.f);
                v0.y = fmaxf(acc[m2][j][1] + by, 0.f);
                v1.x = fmaxf(acc[m2][j][2] + bx, 0.f);
                v1.y = fmaxf(acc[m2][j][3] + by, 0.f);
                *(float2*)(g_e + (size_t)r0*FF + n)     = v0;
                *(float2*)(g_e + (size_t)(r0+8)*FF + n) = v1;
            }
        }
    } else {
        const float* bias = b_lo + l*DD;
        #pragma unroll
        for (int m2 = 0; m2 < 2; m2++) {
            const int rbase = mt*128 + warp_m*32 + m2*16;
            const int rule = rbase >> 4;
            const float m0 = mask[rbase + (lid >> 2)];
            const float m1 = mask[rbase + (lid >> 2) + 8];
            #pragma unroll
            for (int j = 0; j < 8; j++) {
                const int n = warp_n*64 + j*8 + (lid & 3)*2;
                const float bx = bias[n], by = bias[n+1];
                float sx = tanhf(acc[m2][j][0] + bx)*m0 + tanhf(acc[m2][j][2] + bx)*m1;
                float sy = tanhf(acc[m2][j][1] + by)*m0 + tanhf(acc[m2][j][3] + by)*m1;
                sx += __shfl_xor_sync(0xffffffffu, sx, 4);
                sx += __shfl_xor_sync(0xffffffffu, sx, 8);
                sx += __shfl_xor_sync(0xffffffffu, sx, 16);
                sy += __shfl_xor_sync(0xffffffffu, sy, 4);
                sy += __shfl_xor_sync(0xffffffffu, sy, 8);
                sy += __shfl_xor_sync(0xffffffffu, sy, 16);
                if ((lid >> 2) == 0) {   // one writer per (rule,n) per launch
                    g_out_r[rule*DD + n]     += sx;
                    g_out_r[rule*DD + n + 1] += sy;
                }
            }
        }
    }
}

// ---------------- gather: out[tok] = idx<200 ? out_r[idx] : 0 ----------------
__global__ void gather_kernel(const int* __restrict__ idx, float4* __restrict__ out)
{
    const int gid = blockIdx.x * blockDim.x + threadIdx.x;
    if (gid >= TOKENS * (DD/4)) return;
    const int tok = gid >> 5, d4 = gid & 31;
    const int r = idx[tok];
    float4 v = make_float4(0.f, 0.f, 0.f, 0.f);
    if (r < RR) v = ((const float4*)g_out_r)[r*(DD/4) + d4];
    out[gid] = v;
}

// ---------------- launch ----------------
extern "C" void kernel_launch(void* const* d_in, const int* in_sizes, int n_in,
                              void* d_out, int out_size)
{
    const int*   idx        = (const int*)  d_in[0];
    const float* adj        = (const float*)d_in[1];
    const float* init_embed = (const float*)d_in[2];
    const float* node_mask  = (const float*)d_in[3];
    const float* W_ll       = (const float*)d_in[4];
    const float* b_ll       = (const float*)d_in[5];
    const float* W_lo       = (const float*)d_in[6];
    const float* b_lo       = (const float*)d_in[7];
    float* out = (float*)d_out;

    cudaFuncSetAttribute(fused_gemm_kernel,
                         cudaFuncAttributeMaxDynamicSharedMemorySize, SM_BYTES);

    prep_kernel<<<(NUML*FF*FF + 255)/256, 256>>>(W_ll, W_lo);
    for (int l = 0; l < NUML; l++) {
        msg_kernel<<<RR, 256>>>(init_embed, adj, l);
        if (l < NUML - 1)
            fused_gemm_kernel<<<dim3(MTOT/128, 5), 256, SM_BYTES>>>(
                l, 0, b_ll, b_lo, node_mask);
        else
            fused_gemm_kernel<<<dim3(MTOT/128, 1), 256, SM_BYTES>>>(
                l, 1, b_ll, b_lo, node_mask);
    }
    gather_kernel<<<(TOKENS*(DD/4) + 255)/256, 256>>>(idx, (float4*)out);
}

// round 6
// speedup vs baseline: 3.8586x; 1.3810x over previous
#include <cuda_runtime.h>
#include <cuda_bf16.h>
#include <cstdint>

// ---------------- problem constants ----------------
#define RR 200
#define NN 16
#define FF 512
#define DD 128
#define NUML 3
#define TOKENS 4096
#define MTOT (RR*NN)    // 3200
#define KSP (3*FF)      // 1536 split-K
#define KC 64           // K per smem chunk
#define NCHUNK (KSP/KC) // 24

// ---------------- device scratch ----------------
__device__ float g_out_r[RR*DD];
__device__ __nv_bfloat16 g_msgA[MTOT*KSP];         // A' ping
__device__ __nv_bfloat16 g_msgB[MTOT*KSP];         // A' pong
__device__ __nv_bfloat16 g_Wll[NUML*FF*KSP];       // B' = [Bh|Bl|Bh], [l][n][k']
__device__ __nv_bfloat16 g_Wlo[NUML*DD*KSP];

#define SWZ(x) ((x) ^ (((x) >> 3) & 0x70))

__device__ __forceinline__ uint32_t smem_u32(const void* p) {
    uint32_t a;
    asm("{ .reg .u64 t; cvta.to.shared.u64 t, %1; cvt.u32.u64 %0, t; }" : "=r"(a) : "l"(p));
    return a;
}
__device__ __forceinline__ void cp16(uint32_t dst, const void* src) {
    asm volatile("cp.async.cg.shared.global [%0], [%1], 16;" :: "r"(dst), "l"(src));
}
#define CP_COMMIT() asm volatile("cp.async.commit_group;" ::: "memory")
#define CP_WAIT(n)  asm volatile("cp.async.wait_group %0;" :: "n"(n) : "memory")

#define LDSM4(r, addr) \
    asm volatile("ldmatrix.sync.aligned.m8n8.x4.shared.b16 {%0,%1,%2,%3}, [%4];" \
        : "=r"((r)[0]), "=r"((r)[1]), "=r"((r)[2]), "=r"((r)[3]) : "r"(addr))

#define MMA16816(d, a, b0v, b1v) \
    asm volatile("mma.sync.aligned.m16n8k16.row.col.f32.bf16.bf16.f32 " \
        "{%0,%1,%2,%3}, {%4,%5,%6,%7}, {%8,%9}, {%0,%1,%2,%3};" \
        : "+f"((d)[0]), "+f"((d)[1]), "+f"((d)[2]), "+f"((d)[3]) \
        : "r"((a)[0]), "r"((a)[1]), "r"((a)[2]), "r"((a)[3]), "r"(b0v), "r"(b1v))

__device__ __forceinline__ void split_pack(float sx, float sy, uint32_t& hv, uint32_t& lv) {
    __nv_bfloat16 hx = __float2bfloat16(sx), hy = __float2bfloat16(sy);
    __nv_bfloat16 lx = __float2bfloat16(sx - __bfloat162float(hx));
    __nv_bfloat16 ly = __float2bfloat16(sy - __bfloat162float(hy));
    __nv_bfloat162 hp(hx, hy), lp(lx, ly);
    hv = *(uint32_t*)&hp; lv = *(uint32_t*)&lp;
}

// ---------------- prep: coalesced transpose+split of weights ----------------
__global__ __launch_bounds__(256) void prep_kernel(const float* __restrict__ W_ll,
                                                   const float* __restrict__ W_lo)
{
    __shared__ float tile[32][33];
    const int t = threadIdx.x, bx = blockIdx.x, by = blockIdx.y, z = blockIdx.z;
    const int is_lo = (z >= 3);
    if (is_lo && by >= 4) return;
    const int l = is_lo ? z - 3 : z;
    const int k0 = bx*32, n0 = by*32;
    const int nd = is_lo ? DD : FF;
    const float* W = is_lo ? W_lo : W_ll;
    __nv_bfloat16* G = is_lo ? g_Wlo : g_Wll;
    const int nrow = is_lo ? DD : FF;

    #pragma unroll
    for (int u = 0; u < 4; u++) {
        const int idx = t + 256*u;
        const int kk = idx >> 5, nn = idx & 31;
        tile[kk][nn] = W[(size_t)(l*FF + k0 + kk)*nd + n0 + nn];
    }
    __syncthreads();
    #pragma unroll
    for (int u = 0; u < 4; u++) {
        const int idx = t + 256*u;
        const int nn = idx >> 5, kk = idx & 31;
        const float w = tile[kk][nn];
        __nv_bfloat16 hi = __float2bfloat16(w);
        __nv_bfloat16 lo = __float2bfloat16(w - __bfloat162float(hi));
        const size_t base = (size_t)(l*nrow + n0 + nn)*KSP + k0 + kk;
        G[base]          = hi;
        G[base + FF]     = lo;
        G[base + 2*FF]   = hi;
    }
}

// ---------------- layer-0 msg: a@init_embed -> split A' into g_msgA ----------------
__global__ __launch_bounds__(256) void msg0_kernel(const float* __restrict__ init_embed,
                                                   const float* __restrict__ adj)
{
    __shared__ float e_s[NN*132];
    __shared__ float a_s[NN*NN];
    const int rule = blockIdx.x, c0 = blockIdx.y*128, t = threadIdx.x;
    if (blockIdx.y == 0 && blockIdx.x < 100) g_out_r[blockIdx.x*256 + t] = 0.f;
    a_s[t] = adj[rule*256 + t];
    #pragma unroll
    for (int u = 0; u < 2; u++) {
        const int idx = t + 256*u;
        const int row = idx >> 5, q = idx & 31;
        *(float4*)&e_s[row*132 + q*4] =
            *(const float4*)(init_embed + (size_t)(rule*NN + row)*FF + c0 + q*4);
    }
    __syncthreads();
    const int col2 = t & 63, grp = t >> 6;
    float2 ev[16];
    #pragma unroll
    for (int j = 0; j < 16; j++) ev[j] = *(float2*)&e_s[j*132 + col2*2];
    #pragma unroll
    for (int ii = 0; ii < 4; ii++) {
        const int i = grp*4 + ii;
        float sx = 0.f, sy = 0.f;
        #pragma unroll
        for (int j = 0; j < 16; j++) {
            const float av = a_s[i*16 + j];
            sx += av*ev[j].x; sy += av*ev[j].y;
        }
        uint32_t hv, lv; split_pack(sx, sy, hv, lv);
        __nv_bfloat16* p = g_msgA + (size_t)(rule*NN + i)*KSP + c0 + col2*2;
        *(uint32_t*)(p)        = hv;
        *(uint32_t*)(p + FF)   = hv;
        *(uint32_t*)(p + 2*FF) = lv;
    }
}

// ---------------- fused HMMA GEMM (layers 0,1): grid (25,5) ----------------
// by<4 : ll tile (epilogue: relu then NEXT-layer msg into write buffer)
// by==4: lo pool += into g_out_r (full-K, single CTA column -> tanh is exact)
#define SM_A0 0
#define SM_B0 16384
#define SM_A1 32768
#define SM_B1 49152
#define SM_ES 0
#define SM_AS 67584
#define SM_BYTES 75776

__global__ __launch_bounds__(256, 1) void fused_gemm_kernel(
    int l, int abuf,
    const float* __restrict__ b_ll, const float* __restrict__ b_lo,
    const float* __restrict__ mask, const float* __restrict__ adjp)
{
    extern __shared__ char smem[];
    const uint32_t sb = smem_u32(smem);
    const int t = threadIdx.x, lid = t & 31, wid = t >> 5;
    const int warp_m = wid & 3, warp_n = wid >> 2;
    const int mt = blockIdx.x;
    const int mode = (blockIdx.y == 4) ? 1 : 0;
    const int nt = mode ? 0 : blockIdx.y;

    const __nv_bfloat16* msg_r = abuf ? g_msgB : g_msgA;
    __nv_bfloat16*       msg_w = abuf ? g_msgA : g_msgB;

    const __nv_bfloat16* Arow = msg_r + (size_t)mt * 128 * KSP;
    const __nv_bfloat16* Brow = (mode ? (g_Wlo + (size_t)l*DD*KSP)
                                      : (g_Wll + (size_t)l*FF*KSP + (size_t)nt*128*KSP));

    float* a_s2 = (float*)(smem + SM_AS);
    if (mode == 0) {
        #pragma unroll
        for (int u = 0; u < 8; u++)
            a_s2[t + 256*u] = adjp[(size_t)mt*2048 + t + 256*u];
    }

    const uint32_t aoff[2] = {SM_A0, SM_A1}, boff[2] = {SM_B0, SM_B1};
    const int r_ld[4] = { (t + 0) >> 3, (t + 256) >> 3, (t + 512) >> 3, (t + 768) >> 3 };
    const int g_ld = t & 7;
    const uint32_t so_ld[4] = {
        SWZ((uint32_t)(r_ld[0]*128 + g_ld*16)), SWZ((uint32_t)(r_ld[1]*128 + g_ld*16)),
        SWZ((uint32_t)(r_ld[2]*128 + g_ld*16)), SWZ((uint32_t)(r_ld[3]*128 + g_ld*16)) };

    float acc[2][8][4];
    #pragma unroll
    for (int i = 0; i < 2; i++)
        #pragma unroll
        for (int j = 0; j < 8; j++)
            #pragma unroll
            for (int k = 0; k < 4; k++) acc[i][j][k] = 0.f;

    #pragma unroll
    for (int u = 0; u < 4; u++) {
        const size_t gi = (size_t)r_ld[u] * KSP + g_ld*8;
        cp16(sb + SM_A0 + so_ld[u], Arow + gi);
        cp16(sb + SM_B0 + so_ld[u], Brow + gi);
    }
    CP_COMMIT();

    const int lid15 = lid & 15, lidh = lid >> 4;

    for (int c = 0; c < NCHUNK; c++) {
        const int s = c & 1;
        if (c + 1 < NCHUNK) {
            #pragma unroll
            for (int u = 0; u < 4; u++) {
                const size_t gi = (size_t)r_ld[u] * KSP + (c+1)*KC + g_ld*8;
                cp16(sb + aoff[s^1] + so_ld[u], Arow + gi);
                cp16(sb + boff[s^1] + so_ld[u], Brow + gi);
            }
            CP_COMMIT();
            CP_WAIT(1);
        } else {
            CP_WAIT(0);
        }
        __syncthreads();

        #pragma unroll
        for (int ks = 0; ks < 4; ks++) {
            const uint32_t grp = ks*2 + lidh;
            uint32_t af[2][4];
            #pragma unroll
            for (int m2 = 0; m2 < 2; m2++) {
                const uint32_t row = warp_m*32 + m2*16 + lid15;
                LDSM4(af[m2], sb + aoff[s] + SWZ(row*128 + grp*16));
            }
            #pragma unroll
            for (int n4 = 0; n4 < 4; n4++) {
                uint32_t bf[4];
                const uint32_t row = warp_n*64 + n4*16 + lid15;
                LDSM4(bf, sb + boff[s] + SWZ(row*128 + grp*16));
                #pragma unroll
                for (int m2 = 0; m2 < 2; m2++) {
                    MMA16816(acc[m2][n4*2],   af[m2], bf[0], bf[2]);
                    MMA16816(acc[m2][n4*2+1], af[m2], bf[1], bf[3]);
                }
            }
        }
        __syncthreads();
    }

    // ---------------- epilogue ----------------
    if (mode == 0) {
        float* e_s = (float*)(smem + SM_ES);   // [128][132]
        const float* bias = b_ll + l*FF + nt*128;
        #pragma unroll
        for (int m2 = 0; m2 < 2; m2++) {
            const int row = warp_m*32 + m2*16 + (lid >> 2);
            #pragma unroll
            for (int j = 0; j < 8; j++) {
                const int colL = warp_n*64 + j*8 + (lid & 3)*2;
                const float bx = bias[colL], by = bias[colL+1];
                float2 v0, v1;
                v0.x = fmaxf(acc[m2][j][0] + bx, 0.f);
                v0.y = fmaxf(acc[m2][j][1] + by, 0.f);
                v1.x = fmaxf(acc[m2][j][2] + bx, 0.f);
                v1.y = fmaxf(acc[m2][j][3] + by, 0.f);
                *(float2*)&e_s[row*132 + colL]     = v0;
                *(float2*)&e_s[(row+8)*132 + colL] = v1;
            }
        }
        __syncthreads();

        const int col2 = t & 63, grp = t >> 6;
        #pragma unroll
        for (int rr = 0; rr < 2; rr++) {
            const int rl = grp*2 + rr;
            float2 ev[16];
            #pragma unroll
            for (int j = 0; j < 16; j++)
                ev[j] = *(float2*)&e_s[(rl*16 + j)*132 + col2*2];
            const float* arow = a_s2 + rl*256;
            __nv_bfloat16* wbase = msg_w + (size_t)(mt*128 + rl*16)*KSP + nt*128 + col2*2;
            #pragma unroll
            for (int i = 0; i < 16; i++) {
                float sx = 0.f, sy = 0.f;
                #pragma unroll
                for (int j = 0; j < 16; j++) {
                    const float av = arow[i*16 + j];
                    sx += av*ev[j].x; sy += av*ev[j].y;
                }
                uint32_t hv, lv; split_pack(sx, sy, hv, lv);
                __nv_bfloat16* p = wbase + (size_t)i*KSP;
                *(uint32_t*)(p)        = hv;
                *(uint32_t*)(p + FF)   = hv;
                *(uint32_t*)(p + 2*FF) = lv;
            }
        }
    } else {
        const float* bias = b_lo + l*DD;
        #pragma unroll
        for (int m2 = 0; m2 < 2; m2++) {
            const int rbase = mt*128 + warp_m*32 + m2*16;
            const int rule = rbase >> 4;
            const float m0 = mask[rbase + (lid >> 2)];
            const float m1 = mask[rbase + (lid >> 2) + 8];
            #pragma unroll
            for (int j = 0; j < 8; j++) {
                const int n = warp_n*64 + j*8 + (lid & 3)*2;
                const float bx = bias[n], by = bias[n+1];
                float sx = tanhf(acc[m2][j][0] + bx)*m0 + tanhf(acc[m2][j][2] + bx)*m1;
                float sy = tanhf(acc[m2][j][1] + by)*m0 + tanhf(acc[m2][j][3] + by)*m1;
                sx += __shfl_xor_sync(0xffffffffu, sx, 4);
                sx += __shfl_xor_sync(0xffffffffu, sx, 8);
                sx += __shfl_xor_sync(0xffffffffu, sx, 16);
                sy += __shfl_xor_sync(0xffffffffu, sy, 4);
                sy += __shfl_xor_sync(0xffffffffu, sy, 8);
                sy += __shfl_xor_sync(0xffffffffu, sy, 16);
                if ((lid >> 2) == 0) {
                    g_out_r[rule*DD + n]     += sx;
                    g_out_r[rule*DD + n + 1] += sy;
                }
            }
        }
    }
}

// ---------------- layer-2 lo GEMM: M-tile 32, grid 100 (full K per CTA) ----------------
#define SM_LA0 0
#define SM_LA1 4096
#define SM_LB0 8192
#define SM_LB1 24576
#define SM_LO_BYTES 40960

__global__ __launch_bounds__(256, 1) void lo32_kernel(
    int l, int abuf, const float* __restrict__ b_lo, const float* __restrict__ mask)
{
    extern __shared__ char smem[];
    const uint32_t sb = smem_u32(smem);
    const int t = threadIdx.x, lid = t & 31, wid = t >> 5;   // wid = warp_n (0..7)
    const int mt = blockIdx.x;                               // 32-row tile -> 2 rules

    const __nv_bfloat16* msg_r = abuf ? g_msgB : g_msgA;
    const __nv_bfloat16* Arow = msg_r + (size_t)mt * 32 * KSP;
    const __nv_bfloat16* Brow = g_Wlo + (size_t)l*DD*KSP;

    const uint32_t aoff[2] = {SM_LA0, SM_LA1}, boff[2] = {SM_LB0, SM_LB1};
    // A: 256 int4 -> 1/thread; B: 1024 int4 -> 4/thread
    const int ra = t >> 3, g_ld = t & 7;
    const uint32_t so_a = SWZ((uint32_t)(ra*128 + g_ld*16));
    const int r_ld[4] = { (t + 0) >> 3, (t + 256) >> 3, (t + 512) >> 3, (t + 768) >> 3 };
    const uint32_t so_b[4] = {
        SWZ((uint32_t)(r_ld[0]*128 + g_ld*16)), SWZ((uint32_t)(r_ld[1]*128 + g_ld*16)),
        SWZ((uint32_t)(r_ld[2]*128 + g_ld*16)), SWZ((uint32_t)(r_ld[3]*128 + g_ld*16)) };

    float acc[2][2][4];
    #pragma unroll
    for (int i = 0; i < 2; i++)
        #pragma unroll
        for (int j = 0; j < 2; j++)
            #pragma unroll
            for (int k = 0; k < 4; k++) acc[i][j][k] = 0.f;

    cp16(sb + SM_LA0 + so_a, Arow + (size_t)ra*KSP + g_ld*8);
    #pragma unroll
    for (int u = 0; u < 4; u++)
        cp16(sb + SM_LB0 + so_b[u], Brow + (size_t)r_ld[u]*KSP + g_ld*8);
    CP_COMMIT();

    const int lid15 = lid & 15, lidh = lid >> 4;

    for (int c = 0; c < NCHUNK; c++) {
        const int s = c & 1;
        if (c + 1 < NCHUNK) {
            cp16(sb + aoff[s^1] + so_a, Arow + (size_t)ra*KSP + (c+1)*KC + g_ld*8);
            #pragma unroll
            for (int u = 0; u < 4; u++)
                cp16(sb + boff[s^1] + so_b[u], Brow + (size_t)r_ld[u]*KSP + (c+1)*KC + g_ld*8);
            CP_COMMIT();
            CP_WAIT(1);
        } else {
            CP_WAIT(0);
        }
        __syncthreads();

        #pragma unroll
        for (int ks = 0; ks < 4; ks++) {
            const uint32_t grp = ks*2 + lidh;
            uint32_t af[2][4];
            #pragma unroll
            for (int m2 = 0; m2 < 2; m2++) {
                const uint32_t row = m2*16 + lid15;
                LDSM4(af[m2], sb + aoff[s] + SWZ(row*128 + grp*16));
            }
            uint32_t bf[4];
            const uint32_t row = wid*16 + lid15;
            LDSM4(bf, sb + boff[s] + SWZ(row*128 + grp*16));
            #pragma unroll
            for (int m2 = 0; m2 < 2; m2++) {
                MMA16816(acc[m2][0], af[m2], bf[0], bf[2]);
                MMA16816(acc[m2][1], af[m2], bf[1], bf[3]);
            }
        }
        __syncthreads();
    }

    const float* bias = b_lo + l*DD;
    #pragma unroll
    for (int m2 = 0; m2 < 2; m2++) {
        const int rbase = mt*32 + m2*16;
        const int rule = rbase >> 4;
        const float m0 = mask[rbase + (lid >> 2)];
        const float m1 = mask[rbase + (lid >> 2) + 8];
        #pragma unroll
        for (int j = 0; j < 2; j++) {
            const int n = wid*16 + j*8 + (lid & 3)*2;
            const float bx = bias[n], by = bias[n+1];
            float sx = tanhf(acc[m2][j][0] + bx)*m0 + tanhf(acc[m2][j][2] + bx)*m1;
            float sy = tanhf(acc[m2][j][1] + by)*m0 + tanhf(acc[m2][j][3] + by)*m1;
            sx += __shfl_xor_sync(0xffffffffu, sx, 4);
            sx += __shfl_xor_sync(0xffffffffu, sx, 8);
            sx += __shfl_xor_sync(0xffffffffu, sx, 16);
            sy += __shfl_xor_sync(0xffffffffu, sy, 4);
            sy += __shfl_xor_sync(0xffffffffu, sy, 8);
            sy += __shfl_xor_sync(0xffffffffu, sy, 16);
            if ((lid >> 2) == 0) {   // unique (rule, n) writer in this launch
                g_out_r[rule*DD + n]     += sx;
                g_out_r[rule*DD + n + 1] += sy;
            }
        }
    }
}

// ---------------- gather ----------------
__global__ void gather_kernel(const int* __restrict__ idx, float4* __restrict__ out)
{
    const int gid = blockIdx.x * blockDim.x + threadIdx.x;
    if (gid >= TOKENS * (DD/4)) return;
    const int tok = gid >> 5, d4 = gid & 31;
    const int r = idx[tok];
    float4 v = make_float4(0.f, 0.f, 0.f, 0.f);
    if (r < RR) v = ((const float4*)g_out_r)[r*(DD/4) + d4];
    out[gid] = v;
}

// ---------------- launch ----------------
extern "C" void kernel_launch(void* const* d_in, const int* in_sizes, int n_in,
                              void* d_out, int out_size)
{
    const int*   idx        = (const int*)  d_in[0];
    const float* adj        = (const float*)d_in[1];
    const float* init_embed = (const float*)d_in[2];
    const float* node_mask  = (const float*)d_in[3];
    const float* W_ll       = (const float*)d_in[4];
    const float* b_ll       = (const float*)d_in[5];
    const float* W_lo       = (const float*)d_in[6];
    const float* b_lo       = (const float*)d_in[7];
    float* out = (float*)d_out;

    cudaFuncSetAttribute(fused_gemm_kernel,
                         cudaFuncAttributeMaxDynamicSharedMemorySize, SM_BYTES);
    cudaFuncSetAttribute(lo32_kernel,
                         cudaFuncAttributeMaxDynamicSharedMemorySize, SM_LO_BYTES);

    prep_kernel<<<dim3(16,16,6), 256>>>(W_ll, W_lo);
    msg0_kernel<<<dim3(200,4), 256>>>(init_embed, adj);
    fused_gemm_kernel<<<dim3(25,5), 256, SM_BYTES>>>(0, 0, b_ll, b_lo, node_mask, adj);
    fused_gemm_kernel<<<dim3(25,5), 256, SM_BYTES>>>(1, 1, b_ll, b_lo, node_mask, adj);
    lo32_kernel<<<100, 256, SM_LO_BYTES>>>(2, 0, b_lo, node_mask);
    gather_kernel<<<(TOKENS*(DD/4) + 255)/256, 256>>>(idx, (float4*)out);
}

// round 7
// speedup vs baseline: 4.3764x; 1.1342x over previous
#include <cuda_runtime.h>
#include <cuda_bf16.h>
#include <cstdint>

// ---------------- problem constants ----------------
#define RR 200
#define NN 16
#define FF 512
#define DD 128
#define NUML 3
#define TOKENS 4096
#define MTOT (RR*NN)    // 3200
#define KSP (3*FF)      // 1536 split-K
#define NSTAGE 12       // 12 stages x 128 cols

// ---------------- device scratch ----------------
__device__ float g_out_r[RR*DD];
__device__ __nv_bfloat16 g_msgA[MTOT*KSP];         // A' ping
__device__ __nv_bfloat16 g_msgB[MTOT*KSP];         // A' pong
__device__ __nv_bfloat16 g_Wll[NUML*FF*KSP];       // B' = [Bh|Bl|Bh], [l][n][k']
__device__ __nv_bfloat16 g_Wlo[NUML*DD*KSP];

#define SWZ(x) ((x) ^ (((x) >> 3) & 0x70))

__device__ __forceinline__ uint32_t smem_u32(const void* p) {
    uint32_t a;
    asm("{ .reg .u64 t; cvta.to.shared.u64 t, %1; cvt.u32.u64 %0, t; }" : "=r"(a) : "l"(p));
    return a;
}
__device__ __forceinline__ void cp16(uint32_t dst, const void* src) {
    asm volatile("cp.async.cg.shared.global [%0], [%1], 16;" :: "r"(dst), "l"(src));
}
#define CP_COMMIT() asm volatile("cp.async.commit_group;" ::: "memory")
#define CP_WAIT(n)  asm volatile("cp.async.wait_group %0;" :: "n"(n) : "memory")

#define LDSM4(r, addr) \
    asm volatile("ldmatrix.sync.aligned.m8n8.x4.shared.b16 {%0,%1,%2,%3}, [%4];" \
        : "=r"((r)[0]), "=r"((r)[1]), "=r"((r)[2]), "=r"((r)[3]) : "r"(addr))

#define MMA16816(d, a, b0v, b1v) \
    asm volatile("mma.sync.aligned.m16n8k16.row.col.f32.bf16.bf16.f32 " \
        "{%0,%1,%2,%3}, {%4,%5,%6,%7}, {%8,%9}, {%0,%1,%2,%3};" \
        : "+f"((d)[0]), "+f"((d)[1]), "+f"((d)[2]), "+f"((d)[3]) \
        : "r"((a)[0]), "r"((a)[1]), "r"((a)[2]), "r"((a)[3]), "r"(b0v), "r"(b1v))

__device__ __forceinline__ void split_pack(float sx, float sy, uint32_t& hv, uint32_t& lv) {
    __nv_bfloat16 hx = __float2bfloat16(sx), hy = __float2bfloat16(sy);
    __nv_bfloat16 lx = __float2bfloat16(sx - __bfloat162float(hx));
    __nv_bfloat16 ly = __float2bfloat16(sy - __bfloat162float(hy));
    __nv_bfloat162 hp(hx, hy), lp(lx, ly);
    hv = *(uint32_t*)&hp; lv = *(uint32_t*)&lp;
}

// ---------------- merged prep (weights transpose+split) + layer-0 msg ----------------
// blocks [0,1536): prep; blocks [1536, 2336): msg0 (200 rules x 4 col-blocks)
__global__ __launch_bounds__(256) void prep_msg0_kernel(
    const float* __restrict__ W_ll, const float* __restrict__ W_lo,
    const float* __restrict__ init_embed, const float* __restrict__ adj)
{
    __shared__ float sh[2368];
    const int b = blockIdx.x, t = threadIdx.x;
    if (b < 1536) {
        float (*tile)[33] = (float(*)[33])sh;
        const int bx = b & 15, by = (b >> 4) & 15, z = b >> 8;
        const int is_lo = (z >= 3);
        if (is_lo && by >= 4) return;
        const int l = is_lo ? z - 3 : z;
        const int k0 = bx*32, n0 = by*32;
        const int nd = is_lo ? DD : FF;
        const float* W = is_lo ? W_lo : W_ll;
        __nv_bfloat16* G = is_lo ? g_Wlo : g_Wll;
        const int nrow = is_lo ? DD : FF;
        #pragma unroll
        for (int u = 0; u < 4; u++) {
            const int idx = t + 256*u;
            const int kk = idx >> 5, nn = idx & 31;
            tile[kk][nn] = W[(size_t)(l*FF + k0 + kk)*nd + n0 + nn];
        }
        __syncthreads();
        #pragma unroll
        for (int u = 0; u < 4; u++) {
            const int idx = t + 256*u;
            const int nn = idx >> 5, kk = idx & 31;
            const float w = tile[kk][nn];
            __nv_bfloat16 hi = __float2bfloat16(w);
            __nv_bfloat16 lo = __float2bfloat16(w - __bfloat162float(hi));
            const size_t base = (size_t)(l*nrow + n0 + nn)*KSP + k0 + kk;
            G[base]        = hi;
            G[base + FF]   = lo;
            G[base + 2*FF] = hi;
        }
    } else {
        float* e_s = sh;            // 16*132
        float* a_s = sh + 2112;     // 256
        const int idx2 = b - 1536;
        const int rule = idx2 >> 2, c0 = (idx2 & 3)*128;
        if ((idx2 & 3) == 0 && rule < 100) g_out_r[rule*256 + t] = 0.f;
        a_s[t] = adj[rule*256 + t];
        #pragma unroll
        for (int u = 0; u < 2; u++) {
            const int idx = t + 256*u;
            const int row = idx >> 5, q = idx & 31;
            *(float4*)&e_s[row*132 + q*4] =
                *(const float4*)(init_embed + (size_t)(rule*NN + row)*FF + c0 + q*4);
        }
        __syncthreads();
        const int col2 = t & 63, grp = t >> 6;
        float2 ev[16];
        #pragma unroll
        for (int j = 0; j < 16; j++) ev[j] = *(float2*)&e_s[j*132 + col2*2];
        #pragma unroll
        for (int ii = 0; ii < 4; ii++) {
            const int i = grp*4 + ii;
            float sx = 0.f, sy = 0.f;
            #pragma unroll
            for (int j = 0; j < 16; j++) {
                const float av = a_s[i*16 + j];
                sx += av*ev[j].x; sy += av*ev[j].y;
            }
            uint32_t hv, lv; split_pack(sx, sy, hv, lv);
            __nv_bfloat16* p = g_msgA + (size_t)(rule*NN + i)*KSP + c0 + col2*2;
            *(uint32_t*)(p)        = hv;
            *(uint32_t*)(p + FF)   = hv;
            *(uint32_t*)(p + 2*FF) = lv;
        }
    }
}

// ---------------- fused HMMA GEMM (layers 0,1): grid (25,5) ----------------
// by<4 : ll tile (epilogue: relu then NEXT-layer msg into write buffer)
// by==4: lo pool += into g_out_r (full-K -> tanh exact)
// 3-stage ring, 128 cols per stage (2 x 64-col sub-chunks). Stage: A 32K + B 32K.
#define STG_BYTES 65536
#define SM_AS (3*STG_BYTES)          // 196608: adjacency 8KB
#define SM_BYTES (SM_AS + 8192)      // 204800

__global__ __launch_bounds__(256, 1) void fused_gemm_kernel(
    int l, int abuf,
    const float* __restrict__ b_ll, const float* __restrict__ b_lo,
    const float* __restrict__ mask, const float* __restrict__ adjp)
{
    extern __shared__ char smem[];
    const uint32_t sb = smem_u32(smem);
    const int t = threadIdx.x, lid = t & 31, wid = t >> 5;
    const int warp_m = wid & 3, warp_n = wid >> 2;
    const int mt = blockIdx.x;
    const int mode = (blockIdx.y == 4) ? 1 : 0;
    const int nt = mode ? 0 : blockIdx.y;

    const __nv_bfloat16* msg_r = abuf ? g_msgB : g_msgA;
    __nv_bfloat16*       msg_w = abuf ? g_msgA : g_msgB;

    const __nv_bfloat16* Arow = msg_r + (size_t)mt * 128 * KSP;
    const __nv_bfloat16* Brow = (mode ? (g_Wlo + (size_t)l*DD*KSP)
                                      : (g_Wll + (size_t)l*FF*KSP + (size_t)nt*128*KSP));

    float* a_s2 = (float*)(smem + SM_AS);
    if (mode == 0) {
        #pragma unroll
        for (int u = 0; u < 8; u++)
            a_s2[t + 256*u] = adjp[(size_t)mt*2048 + t + 256*u];
    }

    // global->smem load mapping (per 64-col sub-chunk: 1024 int4, 4 per thread)
    const int r_ld[4] = { (t + 0) >> 3, (t + 256) >> 3, (t + 512) >> 3, (t + 768) >> 3 };
    const int g_ld = t & 7;
    const uint32_t so_ld[4] = {
        SWZ((uint32_t)(r_ld[0]*128 + g_ld*16)), SWZ((uint32_t)(r_ld[1]*128 + g_ld*16)),
        SWZ((uint32_t)(r_ld[2]*128 + g_ld*16)), SWZ((uint32_t)(r_ld[3]*128 + g_ld*16)) };

    // hoisted LDSM offsets (loop-invariant)
    const int lid15 = lid & 15, lidh = lid >> 4;
    uint32_t a_off[2][4], b_off[4][4];
    #pragma unroll
    for (int ks = 0; ks < 4; ks++) {
        const uint32_t grp = ks*2 + lidh;
        #pragma unroll
        for (int m2 = 0; m2 < 2; m2++) {
            const uint32_t row = warp_m*32 + m2*16 + lid15;
            a_off[m2][ks] = SWZ(row*128 + grp*16);
        }
        #pragma unroll
        for (int n4 = 0; n4 < 4; n4++) {
            const uint32_t row = warp_n*64 + n4*16 + lid15;
            b_off[n4][ks] = SWZ(row*128 + grp*16);
        }
    }

    float acc[2][8][4];
    #pragma unroll
    for (int i = 0; i < 2; i++)
        #pragma unroll
        for (int j = 0; j < 8; j++)
            #pragma unroll
            for (int k = 0; k < 4; k++) acc[i][j][k] = 0.f;

    auto load_stage = [&](int st, int buf) {
        const uint32_t ab = sb + buf*STG_BYTES;
        #pragma unroll
        for (int h = 0; h < 2; h++) {
            const int ck = st*2 + h;
            #pragma unroll
            for (int u = 0; u < 4; u++) {
                const size_t gi = (size_t)r_ld[u]*KSP + ck*64 + g_ld*8;
                cp16(ab + h*16384 + so_ld[u],         Arow + gi);
                cp16(ab + 32768 + h*16384 + so_ld[u], Brow + gi);
            }
        }
    };

    load_stage(0, 0); CP_COMMIT();
    load_stage(1, 1); CP_COMMIT();

    for (int st = 0; st < NSTAGE; st++) {
        if (st + 2 < NSTAGE) CP_WAIT(1); else CP_WAIT(0);
        __syncthreads();
        if (st + 2 < NSTAGE) { load_stage(st + 2, (st + 2) % 3); CP_COMMIT(); }

        const uint32_t ab = sb + (st % 3)*STG_BYTES;
        #pragma unroll
        for (int h = 0; h < 2; h++) {
            const uint32_t aB = ab + h*16384, bB = ab + 32768 + h*16384;
            #pragma unroll
            for (int ks = 0; ks < 4; ks++) {
                uint32_t af0[4], af1[4];
                LDSM4(af0, aB + a_off[0][ks]);
                LDSM4(af1, aB + a_off[1][ks]);
                #pragma unroll
                for (int n4 = 0; n4 < 4; n4++) {
                    uint32_t bf[4];
                    LDSM4(bf, bB + b_off[n4][ks]);
                    MMA16816(acc[0][n4*2],   af0, bf[0], bf[2]);
                    MMA16816(acc[0][n4*2+1], af0, bf[1], bf[3]);
                    MMA16816(acc[1][n4*2],   af1, bf[0], bf[2]);
                    MMA16816(acc[1][n4*2+1], af1, bf[1], bf[3]);
                }
            }
        }
    }

    // ---------------- epilogue ----------------
    if (mode == 0) {
        float* e_s = (float*)smem;   // [128][132] reuses stage 0/1 buffers (disjoint from stage 2)
        const float* bias = b_ll + l*FF + nt*128;
        #pragma unroll
        for (int m2 = 0; m2 < 2; m2++) {
            const int row = warp_m*32 + m2*16 + (lid >> 2);
            #pragma unroll
            for (int j = 0; j < 8; j++) {
                const int colL = warp_n*64 + j*8 + (lid & 3)*2;
                const float bx = bias[colL], by = bias[colL+1];
                float2 v0, v1;
                v0.x = fmaxf(acc[m2][j][0] + bx, 0.f);
                v0.y = fmaxf(acc[m2][j][1] + by, 0.f);
                v1.x = fmaxf(acc[m2][j][2] + bx, 0.f);
                v1.y = fmaxf(acc[m2][j][3] + by, 0.f);
                *(float2*)&e_s[row*132 + colL]     = v0;
                *(float2*)&e_s[(row+8)*132 + colL] = v1;
            }
        }
        __syncthreads();

        const int col2 = t & 63, grp = t >> 6;
        #pragma unroll
        for (int rr = 0; rr < 2; rr++) {
            const int rl = grp*2 + rr;
            float2 ev[16];
            #pragma unroll
            for (int j = 0; j < 16; j++)
                ev[j] = *(float2*)&e_s[(rl*16 + j)*132 + col2*2];
            const float* arow = a_s2 + rl*256;
            __nv_bfloat16* wbase = msg_w + (size_t)(mt*128 + rl*16)*KSP + nt*128 + col2*2;
            #pragma unroll
            for (int i = 0; i < 16; i++) {
                float sx = 0.f, sy = 0.f;
                #pragma unroll
                for (int j = 0; j < 16; j++) {
                    const float av = arow[i*16 + j];
                    sx += av*ev[j].x; sy += av*ev[j].y;
                }
                uint32_t hv, lv; split_pack(sx, sy, hv, lv);
                __nv_bfloat16* p = wbase + (size_t)i*KSP;
                *(uint32_t*)(p)        = hv;
                *(uint32_t*)(p + FF)   = hv;
                *(uint32_t*)(p + 2*FF) = lv;
            }
        }
    } else {
        const float* bias = b_lo + l*DD;
        #pragma unroll
        for (int m2 = 0; m2 < 2; m2++) {
            const int rbase = mt*128 + warp_m*32 + m2*16;
            const int rule = rbase >> 4;
            const float m0 = mask[rbase + (lid >> 2)];
            const float m1 = mask[rbase + (lid >> 2) + 8];
            #pragma unroll
            for (int j = 0; j < 8; j++) {
                const int n = warp_n*64 + j*8 + (lid & 3)*2;
                const float bx = bias[n], by = bias[n+1];
                float sx = tanhf(acc[m2][j][0] + bx)*m0 + tanhf(acc[m2][j][2] + bx)*m1;
                float sy = tanhf(acc[m2][j][1] + by)*m0 + tanhf(acc[m2][j][3] + by)*m1;
                sx += __shfl_xor_sync(0xffffffffu, sx, 4);
                sx += __shfl_xor_sync(0xffffffffu, sx, 8);
                sx += __shfl_xor_sync(0xffffffffu, sx, 16);
                sy += __shfl_xor_sync(0xffffffffu, sy, 4);
                sy += __shfl_xor_sync(0xffffffffu, sy, 8);
                sy += __shfl_xor_sync(0xffffffffu, sy, 16);
                if ((lid >> 2) == 0) {
                    g_out_r[rule*DD + n]     += sx;
                    g_out_r[rule*DD + n + 1] += sy;
                }
            }
        }
    }
}

// ---------------- layer-2 lo GEMM: M-tile 32, grid 100 (full K per CTA) ----------------
#define SM_LA0 0
#define SM_LA1 4096
#define SM_LB0 8192
#define SM_LB1 24576
#define SM_LO_BYTES 40960
#define KC 64
#define NCHUNK 24

__global__ __launch_bounds__(256, 1) void lo32_kernel(
    int l, int abuf, const float* __restrict__ b_lo, const float* __restrict__ mask)
{
    extern __shared__ char smem[];
    const uint32_t sb = smem_u32(smem);
    const int t = threadIdx.x, lid = t & 31, wid = t >> 5;
    const int mt = blockIdx.x;

    const __nv_bfloat16* msg_r = abuf ? g_msgB : g_msgA;
    const __nv_bfloat16* Arow = msg_r + (size_t)mt * 32 * KSP;
    const __nv_bfloat16* Brow = g_Wlo + (size_t)l*DD*KSP;

    const uint32_t aoff[2] = {SM_LA0, SM_LA1}, boff[2] = {SM_LB0, SM_LB1};
    const int ra = t >> 3, g_ld = t & 7;
    const uint32_t so_a = SWZ((uint32_t)(ra*128 + g_ld*16));
    const int r_ld[4] = { (t + 0) >> 3, (t + 256) >> 3, (t + 512) >> 3, (t + 768) >> 3 };
    const uint32_t so_b[4] = {
        SWZ((uint32_t)(r_ld[0]*128 + g_ld*16)), SWZ((uint32_t)(r_ld[1]*128 + g_ld*16)),
        SWZ((uint32_t)(r_ld[2]*128 + g_ld*16)), SWZ((uint32_t)(r_ld[3]*128 + g_ld*16)) };

    float acc[2][2][4];
    #pragma unroll
    for (int i = 0; i < 2; i++)
        #pragma unroll
        for (int j = 0; j < 2; j++)
            #pragma unroll
            for (int k = 0; k < 4; k++) acc[i][j][k] = 0.f;

    cp16(sb + SM_LA0 + so_a, Arow + (size_t)ra*KSP + g_ld*8);
    #pragma unroll
    for (int u = 0; u < 4; u++)
        cp16(sb + SM_LB0 + so_b[u], Brow + (size_t)r_ld[u]*KSP + g_ld*8);
    CP_COMMIT();

    const int lid15 = lid & 15, lidh = lid >> 4;
    uint32_t a_off[2][4], b_off[4];
    #pragma unroll
    for (int ks = 0; ks < 4; ks++) {
        const uint32_t grp = ks*2 + lidh;
        a_off[0][ks] = SWZ((uint32_t)((lid15)*128 + grp*16));
        a_off[1][ks] = SWZ((uint32_t)((16 + lid15)*128 + grp*16));
        b_off[ks]    = SWZ((uint32_t)((wid*16 + lid15)*128 + grp*16));
    }

    for (int c = 0; c < NCHUNK; c++) {
        const int s = c & 1;
        if (c + 1 < NCHUNK) {
            cp16(sb + aoff[s^1] + so_a, Arow + (size_t)ra*KSP + (c+1)*KC + g_ld*8);
            #pragma unroll
            for (int u = 0; u < 4; u++)
                cp16(sb + boff[s^1] + so_b[u], Brow + (size_t)r_ld[u]*KSP + (c+1)*KC + g_ld*8);
            CP_COMMIT();
            CP_WAIT(1);
        } else {
            CP_WAIT(0);
        }
        __syncthreads();

        #pragma unroll
        for (int ks = 0; ks < 4; ks++) {
            uint32_t af[2][4];
            LDSM4(af[0], sb + aoff[s] + a_off[0][ks]);
            LDSM4(af[1], sb + aoff[s] + a_off[1][ks]);
            uint32_t bf[4];
            LDSM4(bf, sb + boff[s] + b_off[ks]);
            #pragma unroll
            for (int m2 = 0; m2 < 2; m2++) {
                MMA16816(acc[m2][0], af[m2], bf[0], bf[2]);
                MMA16816(acc[m2][1], af[m2], bf[1], bf[3]);
            }
        }
        __syncthreads();
    }

    const float* bias = b_lo + l*DD;
    #pragma unroll
    for (int m2 = 0; m2 < 2; m2++) {
        const int rbase = mt*32 + m2*16;
        const int rule = rbase >> 4;
        const float m0 = mask[rbase + (lid >> 2)];
        const float m1 = mask[rbase + (lid >> 2) + 8];
        #pragma unroll
        for (int j = 0; j < 2; j++) {
            const int n = wid*16 + j*8 + (lid & 3)*2;
            const float bx = bias[n], by = bias[n+1];
            float sx = tanhf(acc[m2][j][0] + bx)*m0 + tanhf(acc[m2][j][2] + bx)*m1;
            float sy = tanhf(acc[m2][j][1] + by)*m0 + tanhf(acc[m2][j][3] + by)*m1;
            sx += __shfl_xor_sync(0xffffffffu, sx, 4);
            sx += __shfl_xor_sync(0xffffffffu, sx, 8);
            sx += __shfl_xor_sync(0xffffffffu, sx, 16);
            sy += __shfl_xor_sync(0xffffffffu, sy, 4);
            sy += __shfl_xor_sync(0xffffffffu, sy, 8);
            sy += __shfl_xor_sync(0xffffffffu, sy, 16);
            if ((lid >> 2) == 0) {
                g_out_r[rule*DD + n]     += sx;
                g_out_r[rule*DD + n + 1] += sy;
            }
        }
    }
}

// ---------------- gather ----------------
__global__ void gather_kernel(const int* __restrict__ idx, float4* __restrict__ out)
{
    const int gid = blockIdx.x * blockDim.x + threadIdx.x;
    if (gid >= TOKENS * (DD/4)) return;
    const int tok = gid >> 5, d4 = gid & 31;
    const int r = idx[tok];
    float4 v = make_float4(0.f, 0.f, 0.f, 0.f);
    if (r < RR) v = ((const float4*)g_out_r)[r*(DD/4) + d4];
    out[gid] = v;
}

// ---------------- launch ----------------
extern "C" void kernel_launch(void* const* d_in, const int* in_sizes, int n_in,
                              void* d_out, int out_size)
{
    const int*   idx        = (const int*)  d_in[0];
    const float* adj        = (const float*)d_in[1];
    const float* init_embed = (const float*)d_in[2];
    const float* node_mask  = (const float*)d_in[3];
    const float* W_ll       = (const float*)d_in[4];
    const float* b_ll       = (const float*)d_in[5];
    const float* W_lo       = (const float*)d_in[6];
    const float* b_lo       = (const float*)d_in[7];
    float* out = (float*)d_out;

    cudaFuncSetAttribute(fused_gemm_kernel,
                         cudaFuncAttributeMaxDynamicSharedMemorySize, SM_BYTES);
    cudaFuncSetAttribute(lo32_kernel,
                         cudaFuncAttributeMaxDynamicSharedMemorySize, SM_LO_BYTES);

    prep_msg0_kernel<<<2336, 256>>>(W_ll, W_lo, init_embed, adj);
    fused_gemm_kernel<<<dim3(25,5), 256, SM_BYTES>>>(0, 0, b_ll, b_lo, node_mask, adj);
    fused_gemm_kernel<<<dim3(25,5), 256, SM_BYTES>>>(1, 1, b_ll, b_lo, node_mask, adj);
    lo32_kernel<<<100, 256, SM_LO_BYTES>>>(2, 0, b_lo, node_mask);
    gather_kernel<<<(TOKENS*(DD/4) + 255)/256, 256>>>(idx, (float4*)out);
}